// round 1
// baseline (speedup 1.0000x reference)
#include <cuda_runtime.h>
#include <math.h>

// Problem constants
#define TT   243
#define PP   17
#define LL   4
#define CC   128
#define HH   8
#define NPT  4
#define DHH  16
#define BB   2
#define LQ   (TT*PP*LL)        // 16524
#define BLQ  (BB*LQ)           // 33048
#define NLVL 5
#define TOK  (BB*TT*PP*NLVL)   // 41310
#define SS   (PP*NLVL)         // 85

// ---------------- scratch (device globals; no allocations) ----------------
__device__ float g_XS  [(size_t)BLQ*CC];
__device__ float g_XN  [(size_t)BLQ*CC];
__device__ float g_Q   [(size_t)BLQ*CC];
__device__ float g_OFF [(size_t)BLQ*256];
__device__ float g_AW  [(size_t)BLQ*CC];
__device__ float g_VAL [(size_t)BLQ*CC];
__device__ float g_O   [(size_t)BLQ*CC];
__device__ float g_XS2 [(size_t)BLQ*CC];
__device__ float g_XCAT[(size_t)TOK*CC];
__device__ float g_XN2 [(size_t)TOK*CC];
__device__ float g_QKV [(size_t)TOK*384];
__device__ float g_ATTO[(size_t)TOK*CC];
__device__ float g_XCAT2[(size_t)TOK*CC];
__device__ float g_XN3 [(size_t)TOK*CC];
__device__ float g_HID [(size_t)TOK*512];

// ---------------- generic SGEMM: out = A(MxK) @ W(NxK)^T + bias (+epi) -----
// epi: 0=none, 1=+res[m*N+n], 2=exact GELU
__global__ void k_gemm(const float* __restrict__ A, const float* __restrict__ W,
                       const float* __restrict__ bias, const float* __restrict__ res,
                       float* __restrict__ out, int M, int N, int K, int epi)
{
    __shared__ float As[16][68];
    __shared__ float Bs[16][68];
    const int tid = threadIdx.x;
    const int tx = tid & 15, ty = tid >> 4;
    const int row0 = blockIdx.y * 64, col0 = blockIdx.x * 64;
    float acc[4][4];
#pragma unroll
    for (int i = 0; i < 4; i++)
#pragma unroll
        for (int j = 0; j < 4; j++) acc[i][j] = 0.f;

    for (int k0 = 0; k0 < K; k0 += 16) {
#pragma unroll
        for (int i = 0; i < 4; i++) {
            int idx = tid + i * 256;         // 0..1023
            int m = idx >> 4, kk = idx & 15;
            int gm = row0 + m;
            As[kk][m] = (gm < M) ? A[(size_t)gm * K + k0 + kk] : 0.f;
            int gn = col0 + m;
            Bs[kk][m] = (gn < N) ? W[(size_t)gn * K + k0 + kk] : 0.f;
        }
        __syncthreads();
#pragma unroll
        for (int kk = 0; kk < 16; kk++) {
            float a[4], b[4];
#pragma unroll
            for (int i = 0; i < 4; i++) a[i] = As[kk][ty * 4 + i];
#pragma unroll
            for (int j = 0; j < 4; j++) b[j] = Bs[kk][tx * 4 + j];
#pragma unroll
            for (int i = 0; i < 4; i++)
#pragma unroll
                for (int j = 0; j < 4; j++)
                    acc[i][j] = fmaf(a[i], b[j], acc[i][j]);
        }
        __syncthreads();
    }
#pragma unroll
    for (int i = 0; i < 4; i++) {
        int gm = row0 + ty * 4 + i;
        if (gm >= M) continue;
#pragma unroll
        for (int j = 0; j < 4; j++) {
            int gn = col0 + tx * 4 + j;
            if (gn >= N) continue;
            float v = acc[i][j] + bias[gn];
            if (epi == 1)      v += res[(size_t)gm * N + gn];
            else if (epi == 2) v = 0.5f * v * (1.0f + erff(v * 0.7071067811865475f));
            out[(size_t)gm * N + gn] = v;
        }
    }
}

// ---------------- LN1 + positional embedding -------------------------------
__global__ void k_ln1(const float* __restrict__ x, const float* __restrict__ pe,
                      const float* __restrict__ lp, const float* __restrict__ g,
                      const float* __restrict__ be)
{
    int row = blockIdx.x;                // b*LQ + lq
    int b = row / LQ; int lq = row - b * LQ;
    int l = lq & 3; int tp = lq >> 2; int p = tp % PP; int t = tp / PP;
    int c = threadIdx.x;
    size_t xi = ((((size_t)((b * TT + t) * PP + p)) * (LL + 1)) + (l + 1)) * CC + c;
    float v = x[xi];
    g_XS[(size_t)row * CC + c] = v;

    __shared__ float sh[8];
    float s = v;
    for (int o = 16; o > 0; o >>= 1) s += __shfl_xor_sync(0xffffffffu, s, o);
    if ((c & 31) == 0) sh[c >> 5] = s;
    __syncthreads();
    float mean = (sh[0] + sh[1] + sh[2] + sh[3]) * (1.f / CC);
    float dv = v - mean;
    float q2 = dv * dv;
    for (int o = 16; o > 0; o >>= 1) q2 += __shfl_xor_sync(0xffffffffu, q2, o);
    if ((c & 31) == 0) sh[4 + (c >> 5)] = q2;
    __syncthreads();
    float var = (sh[4] + sh[5] + sh[6] + sh[7]) * (1.f / CC);
    float xn = dv * rsqrtf(var + 1e-5f) * g[c] + be[c];
    g_XN[(size_t)row * CC + c] = xn;
    g_Q [(size_t)row * CC + c] = xn + pe[(size_t)lq * CC + c] + lp[(size_t)lq * CC + c];
}

// ---------------- deformable sampling + softmax + aggregation -------------
__global__ void k_deform(const float* __restrict__ refp)
{
    int row = blockIdx.x;                // b*LQ + lq
    int b = row / LQ; int lq = row - b * LQ;
    int tp = lq >> 2; int p = tp % PP; int t = tp / PP;
    int tid = threadIdx.x;
    int h = tid >> 4, d = tid & 15;
    float refx = refp[(((size_t)b * TT + t) * PP + p) * 2 + 0];
    float refy = refp[(((size_t)b * TT + t) * PP + p) * 2 + 1];

    const float* awp = g_AW + (size_t)row * CC + h * 16;
    float w[16], mx = -1e30f;
#pragma unroll
    for (int i = 0; i < 16; i++) { w[i] = awp[i]; mx = fmaxf(mx, w[i]); }
    float den = 0.f;
#pragma unroll
    for (int i = 0; i < 16; i++) { w[i] = expf(w[i] - mx); den += w[i]; }
    float inv = 1.f / den;

    const float* offp  = g_OFF + (size_t)row * 256 + h * 32;
    const float* vbase = g_VAL + (size_t)b * LQ * CC + h * 16 + d;
    float acc = 0.f;
#pragma unroll
    for (int l = 0; l < LL; l++) {
#pragma unroll
        for (int pt = 0; pt < NPT; pt++) {
            float ox = offp[(l * 4 + pt) * 2 + 0];
            float oy = offp[(l * 4 + pt) * 2 + 1];
            float fx = refx * PP + ox - 0.5f;   // loc_x * P - 0.5
            float fy = refy * TT + oy - 0.5f;   // loc_y * T - 0.5
            float x0f = floorf(fx), y0f = floorf(fy);
            int x0 = (int)x0f, y0 = (int)y0f;
            float wx1 = fx - x0f, wy1 = fy - y0f;
            float wx0 = 1.f - wx1, wy0 = 1.f - wy1;
            bool xi0 = (x0 >= 0) && (x0 < PP);
            bool xi1 = (x0 + 1 >= 0) && (x0 + 1 < PP);
            bool yi0 = (y0 >= 0) && (y0 < TT);
            bool yi1 = (y0 + 1 >= 0) && (y0 + 1 < TT);
            float v00 = 0.f, v01 = 0.f, v10 = 0.f, v11 = 0.f;
            if (yi0 && xi0) v00 = vbase[((size_t)(y0 * PP + x0) * LL + l) * CC];
            if (yi0 && xi1) v01 = vbase[((size_t)(y0 * PP + x0 + 1) * LL + l) * CC];
            if (yi1 && xi0) v10 = vbase[((size_t)((y0 + 1) * PP + x0) * LL + l) * CC];
            if (yi1 && xi1) v11 = vbase[((size_t)((y0 + 1) * PP + x0 + 1) * LL + l) * CC];
            float sv = v00 * wy0 * wx0 + v01 * wy0 * wx1 + v10 * wy1 * wx0 + v11 * wy1 * wx1;
            acc = fmaf(sv, w[l * 4 + pt], acc);
        }
    }
    g_O[(size_t)row * CC + tid] = acc * inv;
}

// ---------------- build xcat + LN2 -----------------------------------------
__global__ void k_xcat_ln2(const float* __restrict__ x, const float* __restrict__ g,
                           const float* __restrict__ be)
{
    int row = blockIdx.x;                // ((b*T+t)*P+p)*5 + lvl
    int lvl = row % 5; int btp = row / 5;
    int c = threadIdx.x;
    float v;
    if (lvl == 0) {
        v = x[((size_t)btp * NLVL) * CC + c];     // x[b,t,p,0,c]
    } else {
        int p = btp % PP; int bt = btp / PP; int b = bt / TT; int t = bt % TT;
        size_t rxs = (size_t)b * LQ + ((size_t)t * PP + p) * LL + (lvl - 1);
        v = g_XS2[rxs * CC + c];
    }
    g_XCAT[(size_t)row * CC + c] = v;

    __shared__ float sh[8];
    float s = v;
    for (int o = 16; o > 0; o >>= 1) s += __shfl_xor_sync(0xffffffffu, s, o);
    if ((c & 31) == 0) sh[c >> 5] = s;
    __syncthreads();
    float mean = (sh[0] + sh[1] + sh[2] + sh[3]) * (1.f / CC);
    float dv = v - mean;
    float q2 = dv * dv;
    for (int o = 16; o > 0; o >>= 1) q2 += __shfl_xor_sync(0xffffffffu, q2, o);
    if ((c & 31) == 0) sh[4 + (c >> 5)] = q2;
    __syncthreads();
    float var = (sh[4] + sh[5] + sh[6] + sh[7]) * (1.f / CC);
    g_XN2[(size_t)row * CC + c] = dv * rsqrtf(var + 1e-5f) * g[c] + be[c];
}

// ---------------- per-(bt,head) self-attention, S=85, DH=16 ----------------
__global__ void k_attn()
{
    int bt = blockIdx.x, h = blockIdx.y;
    __shared__ float Qs[SS][DHH], Ks[SS][DHH], Vs[SS][DHH];
    int tid = threadIdx.x;
    for (int i = tid; i < SS * DHH; i += 128) {
        int s = i >> 4, d = i & 15;
        const float* base = g_QKV + ((size_t)bt * SS + s) * 384 + h * 16 + d;
        Qs[s][d] = base[0];
        Ks[s][d] = base[128];
        Vs[s][d] = base[256];
    }
    __syncthreads();
    if (tid < SS) {
        float qv[16];
#pragma unroll
        for (int d = 0; d < 16; d++) qv[d] = Qs[tid][d];
        float mx = -1e30f;
        for (int k = 0; k < SS; k++) {
            float sdot = 0.f;
#pragma unroll
            for (int d = 0; d < 16; d++) sdot = fmaf(qv[d], Ks[k][d], sdot);
            mx = fmaxf(mx, sdot * 0.25f);
        }
        float den = 0.f, o[16];
#pragma unroll
        for (int d = 0; d < 16; d++) o[d] = 0.f;
        for (int k = 0; k < SS; k++) {
            float sdot = 0.f;
#pragma unroll
            for (int d = 0; d < 16; d++) sdot = fmaf(qv[d], Ks[k][d], sdot);
            float e = expf(sdot * 0.25f - mx);
            den += e;
#pragma unroll
            for (int d = 0; d < 16; d++) o[d] = fmaf(e, Vs[k][d], o[d]);
        }
        float inv = 1.f / den;
        float* outp = g_ATTO + ((size_t)bt * SS + tid) * CC + h * 16;
#pragma unroll
        for (int d = 0; d < 16; d++) outp[d] = o[d] * inv;
    }
}

// ---------------- LN3 ------------------------------------------------------
__global__ void k_ln3(const float* __restrict__ g, const float* __restrict__ be)
{
    int row = blockIdx.x;
    int c = threadIdx.x;
    float v = g_XCAT2[(size_t)row * CC + c];
    __shared__ float sh[8];
    float s = v;
    for (int o = 16; o > 0; o >>= 1) s += __shfl_xor_sync(0xffffffffu, s, o);
    if ((c & 31) == 0) sh[c >> 5] = s;
    __syncthreads();
    float mean = (sh[0] + sh[1] + sh[2] + sh[3]) * (1.f / CC);
    float dv = v - mean;
    float q2 = dv * dv;
    for (int o = 16; o > 0; o >>= 1) q2 += __shfl_xor_sync(0xffffffffu, q2, o);
    if ((c & 31) == 0) sh[4 + (c >> 5)] = q2;
    __syncthreads();
    float var = (sh[4] + sh[5] + sh[6] + sh[7]) * (1.f / CC);
    g_XN3[(size_t)row * CC + c] = dv * rsqrtf(var + 1e-5f) * g[c] + be[c];
}

// ---------------- host launch ----------------------------------------------
static inline void launch_gemm(const float* A, const float* W, const float* bias,
                               const float* res, float* out, int M, int N, int K, int epi)
{
    dim3 grid((N + 63) / 64, (M + 63) / 64);
    k_gemm<<<grid, 256>>>(A, W, bias, res, out, M, N, K, epi);
}

extern "C" void kernel_launch(void* const* d_in, const int* in_sizes, int n_in,
                              void* d_out, int out_size)
{
    (void)in_sizes; (void)n_in; (void)out_size;
    const float* x        = (const float*)d_in[0];
    const float* refp     = (const float*)d_in[1];
    const float* pe_buf   = (const float*)d_in[2];
    const float* learn_pos= (const float*)d_in[3];
    const float* w_off    = (const float*)d_in[4];
    const float* b_off    = (const float*)d_in[5];
    const float* w_attn   = (const float*)d_in[6];
    const float* b_attn   = (const float*)d_in[7];
    const float* w_val    = (const float*)d_in[8];
    const float* b_val    = (const float*)d_in[9];
    const float* w_out    = (const float*)d_in[10];
    const float* b_out    = (const float*)d_in[11];
    const float* in_w     = (const float*)d_in[12];
    const float* in_b     = (const float*)d_in[13];
    const float* out_w    = (const float*)d_in[14];
    const float* out_b    = (const float*)d_in[15];
    const float* fc1_w    = (const float*)d_in[16];
    const float* fc1_b    = (const float*)d_in[17];
    const float* fc2_w    = (const float*)d_in[18];
    const float* fc2_b    = (const float*)d_in[19];
    const float* g1       = (const float*)d_in[20];
    const float* be1      = (const float*)d_in[21];
    const float* g2       = (const float*)d_in[22];
    const float* be2      = (const float*)d_in[23];
    const float* g3       = (const float*)d_in[24];
    const float* be3      = (const float*)d_in[25];
    float* out = (float*)d_out;

    // device-symbol addresses (scratch)
    float *pXS, *pXN, *pQ, *pOFF, *pAW, *pVAL, *pO, *pXS2, *pXCAT, *pXN2, *pQKV, *pATTO, *pXCAT2, *pXN3, *pHID;
    cudaGetSymbolAddress((void**)&pXS,   g_XS);
    cudaGetSymbolAddress((void**)&pXN,   g_XN);
    cudaGetSymbolAddress((void**)&pQ,    g_Q);
    cudaGetSymbolAddress((void**)&pOFF,  g_OFF);
    cudaGetSymbolAddress((void**)&pAW,   g_AW);
    cudaGetSymbolAddress((void**)&pVAL,  g_VAL);
    cudaGetSymbolAddress((void**)&pO,    g_O);
    cudaGetSymbolAddress((void**)&pXS2,  g_XS2);
    cudaGetSymbolAddress((void**)&pXCAT, g_XCAT);
    cudaGetSymbolAddress((void**)&pXN2,  g_XN2);
    cudaGetSymbolAddress((void**)&pQKV,  g_QKV);
    cudaGetSymbolAddress((void**)&pATTO, g_ATTO);
    cudaGetSymbolAddress((void**)&pXCAT2,g_XCAT2);
    cudaGetSymbolAddress((void**)&pXN3,  g_XN3);
    cudaGetSymbolAddress((void**)&pHID,  g_HID);

    // 1) LN1 + pos-embed
    k_ln1<<<BLQ, 128>>>(x, pe_buf, learn_pos, g1, be1);
    // 2) offsets GEMM (N=256)
    launch_gemm(pQ,  w_off,  b_off,  nullptr, pOFF, BLQ, 256, CC, 0);
    // 3) attention-weight GEMM (N=128)
    launch_gemm(pQ,  w_attn, b_attn, nullptr, pAW,  BLQ, 128, CC, 0);
    // 4) value GEMM (N=128)
    launch_gemm(pXN, w_val,  b_val,  nullptr, pVAL, BLQ, 128, CC, 0);
    // 5) deformable sampling + softmax + weighted sum
    k_deform<<<BLQ, 128>>>(refp);
    // 6) output projection + residual (xs)
    launch_gemm(pO,  w_out,  b_out,  pXS,     pXS2, BLQ, 128, CC, 1);
    // 7) concat level-0 + LN2
    k_xcat_ln2<<<TOK, 128>>>(x, g2, be2);
    // 8) QKV GEMM (N=384)
    launch_gemm(pXN2, in_w,  in_b,   nullptr, pQKV, TOK, 384, CC, 0);
    // 9) self-attention per (bt, head)
    k_attn<<<dim3(BB * TT, HH), 128>>>();
    // 10) attention out-proj + residual (xcat)
    launch_gemm(pATTO, out_w, out_b, pXCAT,   pXCAT2, TOK, 128, CC, 1);
    // 11) LN3
    k_ln3<<<TOK, 128>>>(g3, be3);
    // 12) FC1 + GELU (N=512)
    launch_gemm(pXN3, fc1_w, fc1_b,  nullptr, pHID, TOK, 512, CC, 2);
    // 13) FC2 + residual (xcat2) -> final output
    launch_gemm(pHID, fc2_w, fc2_b,  pXCAT2,  out,  TOK, 128, 512, 1);
}

// round 2
// speedup vs baseline: 1.9651x; 1.9651x over previous
#include <cuda_runtime.h>
#include <math.h>
#include <stdint.h>

// Problem constants
#define TT   243
#define PP   17
#define LL   4
#define CC   128
#define HH   8
#define NPT  4
#define DHH  16
#define BB   2
#define LQ   (TT*PP*LL)        // 16524
#define BLQ  (BB*LQ)           // 33048
#define NLVL 5
#define TOK  (BB*TT*PP*NLVL)   // 41310
#define SS   (PP*NLVL)         // 85

// ---------------- scratch (device globals; no allocations) ----------------
__device__ float g_XS  [(size_t)BLQ*CC];
__device__ float g_XN  [(size_t)BLQ*CC];
__device__ float g_Q   [(size_t)BLQ*CC];
__device__ float g_OFF [(size_t)BLQ*256];
__device__ float g_AW  [(size_t)BLQ*CC];
__device__ float g_VAL [(size_t)BLQ*CC];
__device__ float g_O   [(size_t)BLQ*CC];
__device__ float g_XS2 [(size_t)BLQ*CC];
__device__ float g_XCAT[(size_t)TOK*CC];
__device__ float g_XN2 [(size_t)TOK*CC];
__device__ float g_QKV [(size_t)TOK*384];
__device__ float g_ATTO[(size_t)TOK*CC];
__device__ float g_XCAT2[(size_t)TOK*CC];
__device__ float g_XN3 [(size_t)TOK*CC];
__device__ float g_HID [(size_t)TOK*512];

// ---------------- TF32 tensor-core GEMM ------------------------------------
// out(MxN) = A(MxK) @ W(NxK)^T + bias  (+epi: 1=+res, 2=GELU)
// Tile: BM=128, BN=128, BK=16, 256 threads = 8 warps (4M x 2N), warp 32x64.
// N must be a multiple of 128 (true for all call sites: 128/256/384/512).

__device__ __forceinline__ uint32_t f2tf32(float f) {
    uint32_t u;
    asm("cvt.rna.tf32.f32 %0, %1;" : "=r"(u) : "f"(f));
    return u;
}

__device__ __forceinline__ void mma_tf32(float* c, const uint32_t* a, const uint32_t* b) {
    asm volatile(
        "mma.sync.aligned.m16n8k8.row.col.f32.tf32.tf32.f32 "
        "{%0,%1,%2,%3}, {%4,%5,%6,%7}, {%8,%9}, {%0,%1,%2,%3};\n"
        : "+f"(c[0]), "+f"(c[1]), "+f"(c[2]), "+f"(c[3])
        : "r"(a[0]), "r"(a[1]), "r"(a[2]), "r"(a[3]), "r"(b[0]), "r"(b[1]));
}

#define LDA_S 20   // 16 + 4 pad (floats)

__global__ __launch_bounds__(256) void k_gemm_tc(
    const float* __restrict__ A, const float* __restrict__ W,
    const float* __restrict__ bias, const float* __restrict__ res,
    float* __restrict__ out, int M, int N, int K, int epi)
{
    __shared__ uint32_t As[2][128 * LDA_S];
    __shared__ uint32_t Bs[2][128 * LDA_S];

    const int tid  = threadIdx.x;
    const int lane = tid & 31, warp = tid >> 5;
    const int g = lane >> 2, t = lane & 3;
    const int wm = (warp >> 1) * 32;   // warp M offset within tile
    const int wn = (warp & 1) * 64;    // warp N offset
    const int row0 = blockIdx.y * 128, col0 = blockIdx.x * 128;

    // global-load mapping: 2 float4 per thread per operand per k-tile
    const int m_ld  = tid >> 2;        // 0..63
    const int k4_ld = (tid & 3) * 4;   // 0,4,8,12

    float acc[2][8][4];
#pragma unroll
    for (int mi = 0; mi < 2; mi++)
#pragma unroll
        for (int ni = 0; ni < 8; ni++)
#pragma unroll
            for (int r = 0; r < 4; r++) acc[mi][ni][r] = 0.f;

    const int KT = K >> 4;
    const float4 z4 = make_float4(0.f, 0.f, 0.f, 0.f);
    float4 ar[2], br[2];

    // prefetch k-tile 0
    {
        int gm0 = row0 + m_ld, gm1 = row0 + m_ld + 64;
        ar[0] = (gm0 < M) ? *(const float4*)(A + (size_t)gm0 * K + k4_ld) : z4;
        ar[1] = (gm1 < M) ? *(const float4*)(A + (size_t)gm1 * K + k4_ld) : z4;
        br[0] = *(const float4*)(W + (size_t)(col0 + m_ld) * K + k4_ld);
        br[1] = *(const float4*)(W + (size_t)(col0 + m_ld + 64) * K + k4_ld);
    }
#pragma unroll
    for (int i = 0; i < 2; i++) {
        uint4 ua = make_uint4(f2tf32(ar[i].x), f2tf32(ar[i].y), f2tf32(ar[i].z), f2tf32(ar[i].w));
        uint4 ub = make_uint4(f2tf32(br[i].x), f2tf32(br[i].y), f2tf32(br[i].z), f2tf32(br[i].w));
        *(uint4*)&As[0][(m_ld + i * 64) * LDA_S + k4_ld] = ua;
        *(uint4*)&Bs[0][(m_ld + i * 64) * LDA_S + k4_ld] = ub;
    }
    __syncthreads();

    for (int kt = 0; kt < KT; kt++) {
        const int nb = kt + 1;
        if (nb < KT) {
            int kb = nb * 16 + k4_ld;
            int gm0 = row0 + m_ld, gm1 = row0 + m_ld + 64;
            ar[0] = (gm0 < M) ? *(const float4*)(A + (size_t)gm0 * K + kb) : z4;
            ar[1] = (gm1 < M) ? *(const float4*)(A + (size_t)gm1 * K + kb) : z4;
            br[0] = *(const float4*)(W + (size_t)(col0 + m_ld) * K + kb);
            br[1] = *(const float4*)(W + (size_t)(col0 + m_ld + 64) * K + kb);
        }
        const uint32_t* __restrict__ sa = As[kt & 1];
        const uint32_t* __restrict__ sb = Bs[kt & 1];
#pragma unroll
        for (int k8 = 0; k8 < 2; k8++) {
            const int kk = k8 * 8;
            uint32_t af[2][4], bf[8][2];
#pragma unroll
            for (int mi = 0; mi < 2; mi++) {
                int mb = wm + mi * 16 + g;
                af[mi][0] = sa[(mb    ) * LDA_S + kk + t];
                af[mi][1] = sa[(mb + 8) * LDA_S + kk + t];
                af[mi][2] = sa[(mb    ) * LDA_S + kk + t + 4];
                af[mi][3] = sa[(mb + 8) * LDA_S + kk + t + 4];
            }
#pragma unroll
            for (int ni = 0; ni < 8; ni++) {
                int nbr = wn + ni * 8 + g;
                bf[ni][0] = sb[nbr * LDA_S + kk + t];
                bf[ni][1] = sb[nbr * LDA_S + kk + t + 4];
            }
#pragma unroll
            for (int mi = 0; mi < 2; mi++)
#pragma unroll
                for (int ni = 0; ni < 8; ni++)
                    mma_tf32(acc[mi][ni], af[mi], bf[ni]);
        }
        if (nb < KT) {
#pragma unroll
            for (int i = 0; i < 2; i++) {
                uint4 ua = make_uint4(f2tf32(ar[i].x), f2tf32(ar[i].y), f2tf32(ar[i].z), f2tf32(ar[i].w));
                uint4 ub = make_uint4(f2tf32(br[i].x), f2tf32(br[i].y), f2tf32(br[i].z), f2tf32(br[i].w));
                *(uint4*)&As[nb & 1][(m_ld + i * 64) * LDA_S + k4_ld] = ua;
                *(uint4*)&Bs[nb & 1][(m_ld + i * 64) * LDA_S + k4_ld] = ub;
            }
        }
        __syncthreads();
    }

    // epilogue
#pragma unroll
    for (int mi = 0; mi < 2; mi++) {
#pragma unroll
        for (int r = 0; r < 2; r++) {
            const int gm = row0 + wm + mi * 16 + g + r * 8;
            if (gm >= M) continue;
            float* op = out + (size_t)gm * N;
            const float* rp = res + (size_t)gm * N;
#pragma unroll
            for (int ni = 0; ni < 8; ni++) {
                const int gn = col0 + wn + ni * 8 + 2 * t;
                float v0 = acc[mi][ni][r * 2 + 0] + bias[gn];
                float v1 = acc[mi][ni][r * 2 + 1] + bias[gn + 1];
                if (epi == 1) {
                    v0 += rp[gn];
                    v1 += rp[gn + 1];
                } else if (epi == 2) {
                    v0 = 0.5f * v0 * (1.0f + erff(v0 * 0.7071067811865475f));
                    v1 = 0.5f * v1 * (1.0f + erff(v1 * 0.7071067811865475f));
                }
                float2 v = make_float2(v0, v1);
                *(float2*)&op[gn] = v;
            }
        }
    }
}

// ---------------- LN1 + positional embedding -------------------------------
__global__ void k_ln1(const float* __restrict__ x, const float* __restrict__ pe,
                      const float* __restrict__ lp, const float* __restrict__ g,
                      const float* __restrict__ be)
{
    int row = blockIdx.x;                // b*LQ + lq
    int b = row / LQ; int lq = row - b * LQ;
    int l = lq & 3; int tp = lq >> 2; int p = tp % PP; int t = tp / PP;
    int c = threadIdx.x;
    size_t xi = ((((size_t)((b * TT + t) * PP + p)) * (LL + 1)) + (l + 1)) * CC + c;
    float v = x[xi];
    g_XS[(size_t)row * CC + c] = v;

    __shared__ float sh[8];
    float s = v;
    for (int o = 16; o > 0; o >>= 1) s += __shfl_xor_sync(0xffffffffu, s, o);
    if ((c & 31) == 0) sh[c >> 5] = s;
    __syncthreads();
    float mean = (sh[0] + sh[1] + sh[2] + sh[3]) * (1.f / CC);
    float dv = v - mean;
    float q2 = dv * dv;
    for (int o = 16; o > 0; o >>= 1) q2 += __shfl_xor_sync(0xffffffffu, q2, o);
    if ((c & 31) == 0) sh[4 + (c >> 5)] = q2;
    __syncthreads();
    float var = (sh[4] + sh[5] + sh[6] + sh[7]) * (1.f / CC);
    float xn = dv * rsqrtf(var + 1e-5f) * g[c] + be[c];
    g_XN[(size_t)row * CC + c] = xn;
    g_Q [(size_t)row * CC + c] = xn + pe[(size_t)lq * CC + c] + lp[(size_t)lq * CC + c];
}

// ---------------- deformable sampling + softmax + aggregation -------------
__global__ void k_deform(const float* __restrict__ refp)
{
    int row = blockIdx.x;                // b*LQ + lq
    int b = row / LQ; int lq = row - b * LQ;
    int tp = lq >> 2; int p = tp % PP; int t = tp / PP;
    int tid = threadIdx.x;
    int h = tid >> 4, d = tid & 15;
    float refx = refp[(((size_t)b * TT + t) * PP + p) * 2 + 0];
    float refy = refp[(((size_t)b * TT + t) * PP + p) * 2 + 1];

    const float* awp = g_AW + (size_t)row * CC + h * 16;
    float w[16], mx = -1e30f;
#pragma unroll
    for (int i = 0; i < 16; i++) { w[i] = awp[i]; mx = fmaxf(mx, w[i]); }
    float den = 0.f;
#pragma unroll
    for (int i = 0; i < 16; i++) { w[i] = expf(w[i] - mx); den += w[i]; }
    float inv = 1.f / den;

    const float* offp  = g_OFF + (size_t)row * 256 + h * 32;
    const float* vbase = g_VAL + (size_t)b * LQ * CC + h * 16 + d;
    float acc = 0.f;
#pragma unroll
    for (int l = 0; l < LL; l++) {
#pragma unroll
        for (int pt = 0; pt < NPT; pt++) {
            float ox = offp[(l * 4 + pt) * 2 + 0];
            float oy = offp[(l * 4 + pt) * 2 + 1];
            float fx = refx * PP + ox - 0.5f;   // loc_x * P - 0.5
            float fy = refy * TT + oy - 0.5f;   // loc_y * T - 0.5
            float x0f = floorf(fx), y0f = floorf(fy);
            int x0 = (int)x0f, y0 = (int)y0f;
            float wx1 = fx - x0f, wy1 = fy - y0f;
            float wx0 = 1.f - wx1, wy0 = 1.f - wy1;
            bool xi0 = (x0 >= 0) && (x0 < PP);
            bool xi1 = (x0 + 1 >= 0) && (x0 + 1 < PP);
            bool yi0 = (y0 >= 0) && (y0 < TT);
            bool yi1 = (y0 + 1 >= 0) && (y0 + 1 < TT);
            float v00 = 0.f, v01 = 0.f, v10 = 0.f, v11 = 0.f;
            if (yi0 && xi0) v00 = vbase[((size_t)(y0 * PP + x0) * LL + l) * CC];
            if (yi0 && xi1) v01 = vbase[((size_t)(y0 * PP + x0 + 1) * LL + l) * CC];
            if (yi1 && xi0) v10 = vbase[((size_t)((y0 + 1) * PP + x0) * LL + l) * CC];
            if (yi1 && xi1) v11 = vbase[((size_t)((y0 + 1) * PP + x0 + 1) * LL + l) * CC];
            float sv = v00 * wy0 * wx0 + v01 * wy0 * wx1 + v10 * wy1 * wx0 + v11 * wy1 * wx1;
            acc = fmaf(sv, w[l * 4 + pt], acc);
        }
    }
    g_O[(size_t)row * CC + tid] = acc * inv;
}

// ---------------- build xcat + LN2 -----------------------------------------
__global__ void k_xcat_ln2(const float* __restrict__ x, const float* __restrict__ g,
                           const float* __restrict__ be)
{
    int row = blockIdx.x;                // ((b*T+t)*P+p)*5 + lvl
    int lvl = row % 5; int btp = row / 5;
    int c = threadIdx.x;
    float v;
    if (lvl == 0) {
        v = x[((size_t)btp * NLVL) * CC + c];     // x[b,t,p,0,c]
    } else {
        int p = btp % PP; int bt = btp / PP; int b = bt / TT; int t = bt % TT;
        size_t rxs = (size_t)b * LQ + ((size_t)t * PP + p) * LL + (lvl - 1);
        v = g_XS2[rxs * CC + c];
    }
    g_XCAT[(size_t)row * CC + c] = v;

    __shared__ float sh[8];
    float s = v;
    for (int o = 16; o > 0; o >>= 1) s += __shfl_xor_sync(0xffffffffu, s, o);
    if ((c & 31) == 0) sh[c >> 5] = s;
    __syncthreads();
    float mean = (sh[0] + sh[1] + sh[2] + sh[3]) * (1.f / CC);
    float dv = v - mean;
    float q2 = dv * dv;
    for (int o = 16; o > 0; o >>= 1) q2 += __shfl_xor_sync(0xffffffffu, q2, o);
    if ((c & 31) == 0) sh[4 + (c >> 5)] = q2;
    __syncthreads();
    float var = (sh[4] + sh[5] + sh[6] + sh[7]) * (1.f / CC);
    g_XN2[(size_t)row * CC + c] = dv * rsqrtf(var + 1e-5f) * g[c] + be[c];
}

// ---------------- per-(bt,head) self-attention, S=85, DH=16 ----------------
__global__ void k_attn()
{
    int bt = blockIdx.x, h = blockIdx.y;
    __shared__ float Qs[SS][DHH], Ks[SS][DHH], Vs[SS][DHH];
    int tid = threadIdx.x;
    for (int i = tid; i < SS * DHH; i += 128) {
        int s = i >> 4, d = i & 15;
        const float* base = g_QKV + ((size_t)bt * SS + s) * 384 + h * 16 + d;
        Qs[s][d] = base[0];
        Ks[s][d] = base[128];
        Vs[s][d] = base[256];
    }
    __syncthreads();
    if (tid < SS) {
        float qv[16];
#pragma unroll
        for (int d = 0; d < 16; d++) qv[d] = Qs[tid][d];
        float mx = -1e30f;
        for (int k = 0; k < SS; k++) {
            float sdot = 0.f;
#pragma unroll
            for (int d = 0; d < 16; d++) sdot = fmaf(qv[d], Ks[k][d], sdot);
            mx = fmaxf(mx, sdot * 0.25f);
        }
        float den = 0.f, o[16];
#pragma unroll
        for (int d = 0; d < 16; d++) o[d] = 0.f;
        for (int k = 0; k < SS; k++) {
            float sdot = 0.f;
#pragma unroll
            for (int d = 0; d < 16; d++) sdot = fmaf(qv[d], Ks[k][d], sdot);
            float e = expf(sdot * 0.25f - mx);
            den += e;
#pragma unroll
            for (int d = 0; d < 16; d++) o[d] = fmaf(e, Vs[k][d], o[d]);
        }
        float inv = 1.f / den;
        float* outp = g_ATTO + ((size_t)bt * SS + tid) * CC + h * 16;
#pragma unroll
        for (int d = 0; d < 16; d++) outp[d] = o[d] * inv;
    }
}

// ---------------- LN3 ------------------------------------------------------
__global__ void k_ln3(const float* __restrict__ g, const float* __restrict__ be)
{
    int row = blockIdx.x;
    int c = threadIdx.x;
    float v = g_XCAT2[(size_t)row * CC + c];
    __shared__ float sh[8];
    float s = v;
    for (int o = 16; o > 0; o >>= 1) s += __shfl_xor_sync(0xffffffffu, s, o);
    if ((c & 31) == 0) sh[c >> 5] = s;
    __syncthreads();
    float mean = (sh[0] + sh[1] + sh[2] + sh[3]) * (1.f / CC);
    float dv = v - mean;
    float q2 = dv * dv;
    for (int o = 16; o > 0; o >>= 1) q2 += __shfl_xor_sync(0xffffffffu, q2, o);
    if ((c & 31) == 0) sh[4 + (c >> 5)] = q2;
    __syncthreads();
    float var = (sh[4] + sh[5] + sh[6] + sh[7]) * (1.f / CC);
    g_XN3[(size_t)row * CC + c] = dv * rsqrtf(var + 1e-5f) * g[c] + be[c];
}

// ---------------- host launch ----------------------------------------------
static inline void launch_gemm(const float* A, const float* W, const float* bias,
                               const float* res, float* out, int M, int N, int K, int epi)
{
    dim3 grid(N / 128, (M + 127) / 128);
    k_gemm_tc<<<grid, 256>>>(A, W, bias, res ? res : A, out, M, N, K, epi);
}

extern "C" void kernel_launch(void* const* d_in, const int* in_sizes, int n_in,
                              void* d_out, int out_size)
{
    (void)in_sizes; (void)n_in; (void)out_size;
    const float* x        = (const float*)d_in[0];
    const float* refp     = (const float*)d_in[1];
    const float* pe_buf   = (const float*)d_in[2];
    const float* learn_pos= (const float*)d_in[3];
    const float* w_off    = (const float*)d_in[4];
    const float* b_off    = (const float*)d_in[5];
    const float* w_attn   = (const float*)d_in[6];
    const float* b_attn   = (const float*)d_in[7];
    const float* w_val    = (const float*)d_in[8];
    const float* b_val    = (const float*)d_in[9];
    const float* w_out    = (const float*)d_in[10];
    const float* b_out    = (const float*)d_in[11];
    const float* in_w     = (const float*)d_in[12];
    const float* in_b     = (const float*)d_in[13];
    const float* out_w    = (const float*)d_in[14];
    const float* out_b    = (const float*)d_in[15];
    const float* fc1_w    = (const float*)d_in[16];
    const float* fc1_b    = (const float*)d_in[17];
    const float* fc2_w    = (const float*)d_in[18];
    const float* fc2_b    = (const float*)d_in[19];
    const float* g1       = (const float*)d_in[20];
    const float* be1      = (const float*)d_in[21];
    const float* g2       = (const float*)d_in[22];
    const float* be2      = (const float*)d_in[23];
    const float* g3       = (const float*)d_in[24];
    const float* be3      = (const float*)d_in[25];
    float* out = (float*)d_out;

    // device-symbol addresses (scratch)
    float *pXS, *pXN, *pQ, *pOFF, *pAW, *pVAL, *pO, *pXS2, *pXCAT, *pXN2, *pQKV, *pATTO, *pXCAT2, *pXN3, *pHID;
    cudaGetSymbolAddress((void**)&pXS,   g_XS);
    cudaGetSymbolAddress((void**)&pXN,   g_XN);
    cudaGetSymbolAddress((void**)&pQ,    g_Q);
    cudaGetSymbolAddress((void**)&pOFF,  g_OFF);
    cudaGetSymbolAddress((void**)&pAW,   g_AW);
    cudaGetSymbolAddress((void**)&pVAL,  g_VAL);
    cudaGetSymbolAddress((void**)&pO,    g_O);
    cudaGetSymbolAddress((void**)&pXS2,  g_XS2);
    cudaGetSymbolAddress((void**)&pXCAT, g_XCAT);
    cudaGetSymbolAddress((void**)&pXN2,  g_XN2);
    cudaGetSymbolAddress((void**)&pQKV,  g_QKV);
    cudaGetSymbolAddress((void**)&pATTO, g_ATTO);
    cudaGetSymbolAddress((void**)&pXCAT2,g_XCAT2);
    cudaGetSymbolAddress((void**)&pXN3,  g_XN3);
    cudaGetSymbolAddress((void**)&pHID,  g_HID);

    // 1) LN1 + pos-embed
    k_ln1<<<BLQ, 128>>>(x, pe_buf, learn_pos, g1, be1);
    // 2) offsets GEMM (N=256)
    launch_gemm(pQ,  w_off,  b_off,  nullptr, pOFF, BLQ, 256, CC, 0);
    // 3) attention-weight GEMM (N=128)
    launch_gemm(pQ,  w_attn, b_attn, nullptr, pAW,  BLQ, 128, CC, 0);
    // 4) value GEMM (N=128)
    launch_gemm(pXN, w_val,  b_val,  nullptr, pVAL, BLQ, 128, CC, 0);
    // 5) deformable sampling + softmax + weighted sum
    k_deform<<<BLQ, 128>>>(refp);
    // 6) output projection + residual (xs)
    launch_gemm(pO,  w_out,  b_out,  pXS,     pXS2, BLQ, 128, CC, 1);
    // 7) concat level-0 + LN2
    k_xcat_ln2<<<TOK, 128>>>(x, g2, be2);
    // 8) QKV GEMM (N=384)
    launch_gemm(pXN2, in_w,  in_b,   nullptr, pQKV, TOK, 384, CC, 0);
    // 9) self-attention per (bt, head)
    k_attn<<<dim3(BB * TT, HH), 128>>>();
    // 10) attention out-proj + residual (xcat)
    launch_gemm(pATTO, out_w, out_b, pXCAT,   pXCAT2, TOK, 128, CC, 1);
    // 11) LN3
    k_ln3<<<TOK, 128>>>(g3, be3);
    // 12) FC1 + GELU (N=512)
    launch_gemm(pXN3, fc1_w, fc1_b,  nullptr, pHID, TOK, 512, CC, 2);
    // 13) FC2 + residual (xcat2) -> final output
    launch_gemm(pHID, fc2_w, fc2_b,  pXCAT2,  out,  TOK, 128, 512, 1);
}

// round 3
// speedup vs baseline: 2.4468x; 1.2451x over previous
#include <cuda_runtime.h>
#include <cuda_fp16.h>
#include <math.h>
#include <stdint.h>

// Problem constants
#define TT   243
#define PP   17
#define LL   4
#define CC   128
#define HH   8
#define NPT  4
#define DHH  16
#define BB   2
#define LQ   (TT*PP*LL)        // 16524
#define BLQ  (BB*LQ)           // 33048
#define NLVL 5
#define TOK  (BB*TT*PP*NLVL)   // 41310
#define SS   (PP*NLVL)         // 85

// ---------------- scratch (device globals; no allocations) ----------------
__device__ float  g_XS  [(size_t)BLQ*CC];      // residual (fp32)
__device__ float  g_OFF [(size_t)BLQ*256];
__device__ float  g_AW  [(size_t)BLQ*CC];
__device__ float  g_VAL [(size_t)BLQ*CC];
__device__ float  g_XS2 [(size_t)BLQ*CC];
__device__ float  g_XCAT[(size_t)TOK*CC];
__device__ float  g_QKV [(size_t)TOK*384];
__device__ float  g_XCAT2[(size_t)TOK*CC];
// fp16 activation buffers (GEMM operands)
__device__ __half g_Qh  [(size_t)BLQ*CC];
__device__ __half g_XNh [(size_t)BLQ*CC];
__device__ __half g_Oh  [(size_t)BLQ*CC];
__device__ __half g_XN2h[(size_t)TOK*CC];
__device__ __half g_ATTOh[(size_t)TOK*CC];
__device__ __half g_XN3h[(size_t)TOK*CC];
__device__ __half g_HIDh[(size_t)TOK*512];
// fp16 weights, packed
#define WOFF_OFF   0
#define WOFF_ATTN  32768
#define WOFF_VAL   49152
#define WOFF_OUT   65536
#define WOFF_IN    81920
#define WOFF_OUTW  131072
#define WOFF_FC1   147456
#define WOFF_FC2   212992
#define WTOTAL     278528
__device__ __half g_Wh[WTOTAL];

// ---------------- fp16 tensor-core GEMM ------------------------------------
// out(MxN) = A(MxK) @ W(NxK)^T + bias(+epi). A,W fp16; acc fp32.
// Tile BM=128 BN=128 BK=64(halves). 256 thr = 8 warps (4M x 2N), warp 32x64.
// smem: 2 stages x (16KB A + 16KB B) = 64KB dynamic, SW128 swizzle.

__device__ __forceinline__ void cpa16(uint32_t dst, const void* src, bool valid) {
    int sz = valid ? 16 : 0;
    asm volatile("cp.async.cg.shared.global [%0], [%1], 16, %2;\n"
                 :: "r"(dst), "l"(src), "r"(sz));
}
#define CP_COMMIT() asm volatile("cp.async.commit_group;\n" ::: "memory")
#define CP_WAIT(n)  asm volatile("cp.async.wait_group %0;\n" :: "n"(n) : "memory")

__device__ __forceinline__ void ldm4(uint32_t* r, uint32_t addr) {
    asm volatile("ldmatrix.sync.aligned.m8n8.x4.shared.b16 {%0,%1,%2,%3}, [%4];\n"
                 : "=r"(r[0]), "=r"(r[1]), "=r"(r[2]), "=r"(r[3]) : "r"(addr));
}
__device__ __forceinline__ void mma16(float* c, const uint32_t* a, const uint32_t* b) {
    asm volatile("mma.sync.aligned.m16n8k16.row.col.f32.f16.f16.f32 "
                 "{%0,%1,%2,%3},{%4,%5,%6,%7},{%8,%9},{%0,%1,%2,%3};\n"
                 : "+f"(c[0]), "+f"(c[1]), "+f"(c[2]), "+f"(c[3])
                 : "r"(a[0]), "r"(a[1]), "r"(a[2]), "r"(a[3]), "r"(b[0]), "r"(b[1]));
}

__device__ __forceinline__ void gemm_load_stage(
    const __half* __restrict__ A, const __half* __restrict__ W, uint32_t sb,
    int s, int kt, int row0, int col0, int M, int K, int tid)
{
    const int r0 = tid >> 3, ck = tid & 7;
#pragma unroll
    for (int i = 0; i < 4; i++) {
        int r = r0 + i * 32;
        uint32_t swoff = (uint32_t)(r * 128 + ((ck ^ (r & 7)) * 16));
        int gm = row0 + r;
        const __half* srcA = A + (size_t)gm * K + (size_t)kt * 64 + ck * 8;
        cpa16(sb + s * 32768 + swoff, srcA, gm < M);
        const __half* srcB = W + (size_t)(col0 + r) * K + (size_t)kt * 64 + ck * 8;
        cpa16(sb + s * 32768 + 16384 + swoff, srcB, true);
    }
}

__global__ __launch_bounds__(256, 2) void k_gemm_h(
    const __half* __restrict__ A, const __half* __restrict__ W,
    const float* __restrict__ bias, const float* __restrict__ res,
    void* __restrict__ outp, int M, int N, int K, int epi, int outHalf)
{
    extern __shared__ __align__(1024) char sm[];
    uint32_t sb = (uint32_t)__cvta_generic_to_shared(sm);
    const int tid = threadIdx.x, lane = tid & 31, warp = tid >> 5;
    const int g = lane >> 2, t = lane & 3;
    const int wm = (warp >> 1) * 32, wn = (warp & 1) * 64;
    const int row0 = blockIdx.y * 128, col0 = blockIdx.x * 128;
    const int KT = K >> 6;

    float acc[2][8][4];
#pragma unroll
    for (int mi = 0; mi < 2; mi++)
#pragma unroll
        for (int ni = 0; ni < 8; ni++)
#pragma unroll
            for (int r = 0; r < 4; r++) acc[mi][ni][r] = 0.f;

    gemm_load_stage(A, W, sb, 0, 0, row0, col0, M, K, tid);
    CP_COMMIT();

    for (int kt = 0; kt < KT; kt++) {
        const int s = kt & 1;
        if (kt + 1 < KT) {
            gemm_load_stage(A, W, sb, s ^ 1, kt + 1, row0, col0, M, K, tid);
            CP_COMMIT();
            CP_WAIT(1);
        } else {
            CP_WAIT(0);
        }
        __syncthreads();

        const uint32_t aS = sb + s * 32768;
        const uint32_t bS = aS + 16384;
        const int rlow = lane & 15, hi = lane >> 4;
#pragma unroll
        for (int kk = 0; kk < 4; kk++) {
            uint32_t af[2][4];
#pragma unroll
            for (int mi = 0; mi < 2; mi++) {
                int r = wm + mi * 16 + rlow;
                int ck = kk * 2 + hi;
                ldm4(af[mi], aS + (uint32_t)(r * 128 + ((ck ^ (r & 7)) * 16)));
            }
            uint32_t bf[8][2];
#pragma unroll
            for (int nj = 0; nj < 4; nj++) {
                int r = wn + nj * 16 + rlow;
                int ck = kk * 2 + hi;
                uint32_t q[4];
                ldm4(q, bS + (uint32_t)(r * 128 + ((ck ^ (r & 7)) * 16)));
                bf[nj * 2 + 0][0] = q[0]; bf[nj * 2 + 0][1] = q[2];
                bf[nj * 2 + 1][0] = q[1]; bf[nj * 2 + 1][1] = q[3];
            }
#pragma unroll
            for (int mi = 0; mi < 2; mi++)
#pragma unroll
                for (int ni = 0; ni < 8; ni++)
                    mma16(acc[mi][ni], af[mi], bf[ni]);
        }
        __syncthreads();
    }

    // epilogue (fp32 bias/res; fp32 or fp16 stores)
#pragma unroll
    for (int mi = 0; mi < 2; mi++) {
#pragma unroll
        for (int r = 0; r < 2; r++) {
            const int gm = row0 + wm + mi * 16 + g + r * 8;
            if (gm >= M) continue;
            const float* rp = res + (size_t)gm * N;
#pragma unroll
            for (int ni = 0; ni < 8; ni++) {
                const int gn = col0 + wn + ni * 8 + 2 * t;
                float v0 = acc[mi][ni][r * 2 + 0] + bias[gn];
                float v1 = acc[mi][ni][r * 2 + 1] + bias[gn + 1];
                if (epi == 1) {
                    v0 += rp[gn];
                    v1 += rp[gn + 1];
                } else if (epi == 2) {
                    v0 = 0.5f * v0 * (1.0f + erff(v0 * 0.7071067811865475f));
                    v1 = 0.5f * v1 * (1.0f + erff(v1 * 0.7071067811865475f));
                }
                if (outHalf) {
                    __half2 h2 = __floats2half2_rn(v0, v1);
                    *(__half2*)((__half*)outp + (size_t)gm * N + gn) = h2;
                } else {
                    *(float2*)((float*)outp + (size_t)gm * N + gn) = make_float2(v0, v1);
                }
            }
        }
    }
}

// ---------------- weight conversion (fp32 -> fp16, packed) -----------------
__global__ void k_cvt_w(const float* __restrict__ w0, const float* __restrict__ w1,
                        const float* __restrict__ w2, const float* __restrict__ w3,
                        const float* __restrict__ w4, const float* __restrict__ w5,
                        const float* __restrict__ w6, const float* __restrict__ w7)
{
    for (int idx = blockIdx.x * blockDim.x + threadIdx.x; idx < WTOTAL;
         idx += gridDim.x * blockDim.x) {
        const float* src; int off;
        if      (idx < WOFF_ATTN) { src = w0; off = idx; }
        else if (idx < WOFF_VAL ) { src = w1; off = idx - WOFF_ATTN; }
        else if (idx < WOFF_OUT ) { src = w2; off = idx - WOFF_VAL; }
        else if (idx < WOFF_IN  ) { src = w3; off = idx - WOFF_OUT; }
        else if (idx < WOFF_OUTW) { src = w4; off = idx - WOFF_IN; }
        else if (idx < WOFF_FC1 ) { src = w5; off = idx - WOFF_OUTW; }
        else if (idx < WOFF_FC2 ) { src = w6; off = idx - WOFF_FC1; }
        else                      { src = w7; off = idx - WOFF_FC2; }
        g_Wh[idx] = __float2half_rn(src[off]);
    }
}

// ---------------- LN1 + positional embedding (fp16 outputs) ----------------
__global__ void k_ln1(const float* __restrict__ x, const float* __restrict__ pe,
                      const float* __restrict__ lp, const float* __restrict__ g,
                      const float* __restrict__ be)
{
    int row = blockIdx.x;
    int b = row / LQ; int lq = row - b * LQ;
    int l = lq & 3; int tp = lq >> 2; int p = tp % PP; int t = tp / PP;
    int c = threadIdx.x;
    size_t xi = ((((size_t)((b * TT + t) * PP + p)) * (LL + 1)) + (l + 1)) * CC + c;
    float v = x[xi];
    g_XS[(size_t)row * CC + c] = v;

    __shared__ float sh[8];
    float s = v;
    for (int o = 16; o > 0; o >>= 1) s += __shfl_xor_sync(0xffffffffu, s, o);
    if ((c & 31) == 0) sh[c >> 5] = s;
    __syncthreads();
    float mean = (sh[0] + sh[1] + sh[2] + sh[3]) * (1.f / CC);
    float dv = v - mean;
    float q2 = dv * dv;
    for (int o = 16; o > 0; o >>= 1) q2 += __shfl_xor_sync(0xffffffffu, q2, o);
    if ((c & 31) == 0) sh[4 + (c >> 5)] = q2;
    __syncthreads();
    float var = (sh[4] + sh[5] + sh[6] + sh[7]) * (1.f / CC);
    float xn = dv * rsqrtf(var + 1e-5f) * g[c] + be[c];
    g_XNh[(size_t)row * CC + c] = __float2half_rn(xn);
    g_Qh [(size_t)row * CC + c] = __float2half_rn(xn + pe[(size_t)lq * CC + c] + lp[(size_t)lq * CC + c]);
}

// ---------------- deformable sampling + softmax + aggregation -------------
__global__ void k_deform(const float* __restrict__ refp)
{
    int row = blockIdx.x;
    int b = row / LQ; int lq = row - b * LQ;
    int tp = lq >> 2; int p = tp % PP; int t = tp / PP;
    int tid = threadIdx.x;
    int h = tid >> 4, d = tid & 15;
    float refx = refp[(((size_t)b * TT + t) * PP + p) * 2 + 0];
    float refy = refp[(((size_t)b * TT + t) * PP + p) * 2 + 1];

    const float* awp = g_AW + (size_t)row * CC + h * 16;
    float w[16], mx = -1e30f;
#pragma unroll
    for (int i = 0; i < 16; i++) { w[i] = awp[i]; mx = fmaxf(mx, w[i]); }
    float den = 0.f;
#pragma unroll
    for (int i = 0; i < 16; i++) { w[i] = expf(w[i] - mx); den += w[i]; }
    float inv = 1.f / den;

    const float* offp  = g_OFF + (size_t)row * 256 + h * 32;
    const float* vbase = g_VAL + (size_t)b * LQ * CC + h * 16 + d;
    float acc = 0.f;
#pragma unroll
    for (int l = 0; l < LL; l++) {
#pragma unroll
        for (int pt = 0; pt < NPT; pt++) {
            float ox = offp[(l * 4 + pt) * 2 + 0];
            float oy = offp[(l * 4 + pt) * 2 + 1];
            float fx = refx * PP + ox - 0.5f;
            float fy = refy * TT + oy - 0.5f;
            float x0f = floorf(fx), y0f = floorf(fy);
            int x0 = (int)x0f, y0 = (int)y0f;
            float wx1 = fx - x0f, wy1 = fy - y0f;
            float wx0 = 1.f - wx1, wy0 = 1.f - wy1;
            bool xi0 = (x0 >= 0) && (x0 < PP);
            bool xi1 = (x0 + 1 >= 0) && (x0 + 1 < PP);
            bool yi0 = (y0 >= 0) && (y0 < TT);
            bool yi1 = (y0 + 1 >= 0) && (y0 + 1 < TT);
            float v00 = 0.f, v01 = 0.f, v10 = 0.f, v11 = 0.f;
            if (yi0 && xi0) v00 = vbase[((size_t)(y0 * PP + x0) * LL + l) * CC];
            if (yi0 && xi1) v01 = vbase[((size_t)(y0 * PP + x0 + 1) * LL + l) * CC];
            if (yi1 && xi0) v10 = vbase[((size_t)((y0 + 1) * PP + x0) * LL + l) * CC];
            if (yi1 && xi1) v11 = vbase[((size_t)((y0 + 1) * PP + x0 + 1) * LL + l) * CC];
            float sv = v00 * wy0 * wx0 + v01 * wy0 * wx1 + v10 * wy1 * wx0 + v11 * wy1 * wx1;
            acc = fmaf(sv, w[l * 4 + pt], acc);
        }
    }
    g_Oh[(size_t)row * CC + tid] = __float2half_rn(acc * inv);
}

// ---------------- build xcat + LN2 -----------------------------------------
__global__ void k_xcat_ln2(const float* __restrict__ x, const float* __restrict__ g,
                           const float* __restrict__ be)
{
    int row = blockIdx.x;
    int lvl = row % 5; int btp = row / 5;
    int c = threadIdx.x;
    float v;
    if (lvl == 0) {
        v = x[((size_t)btp * NLVL) * CC + c];
    } else {
        int p = btp % PP; int bt = btp / PP; int b = bt / TT; int t = bt % TT;
        size_t rxs = (size_t)b * LQ + ((size_t)t * PP + p) * LL + (lvl - 1);
        v = g_XS2[rxs * CC + c];
    }
    g_XCAT[(size_t)row * CC + c] = v;

    __shared__ float sh[8];
    float s = v;
    for (int o = 16; o > 0; o >>= 1) s += __shfl_xor_sync(0xffffffffu, s, o);
    if ((c & 31) == 0) sh[c >> 5] = s;
    __syncthreads();
    float mean = (sh[0] + sh[1] + sh[2] + sh[3]) * (1.f / CC);
    float dv = v - mean;
    float q2 = dv * dv;
    for (int o = 16; o > 0; o >>= 1) q2 += __shfl_xor_sync(0xffffffffu, q2, o);
    if ((c & 31) == 0) sh[4 + (c >> 5)] = q2;
    __syncthreads();
    float var = (sh[4] + sh[5] + sh[6] + sh[7]) * (1.f / CC);
    g_XN2h[(size_t)row * CC + c] = __float2half_rn(dv * rsqrtf(var + 1e-5f) * g[c] + be[c]);
}

// ---------------- per-(bt,head) self-attention, S=85, DH=16 ----------------
__global__ void k_attn()
{
    int bt = blockIdx.x, h = blockIdx.y;
    __shared__ float Qs[SS][DHH], Ks[SS][DHH], Vs[SS][DHH];
    int tid = threadIdx.x;
    for (int i = tid; i < SS * DHH; i += 128) {
        int s = i >> 4, d = i & 15;
        const float* base = g_QKV + ((size_t)bt * SS + s) * 384 + h * 16 + d;
        Qs[s][d] = base[0];
        Ks[s][d] = base[128];
        Vs[s][d] = base[256];
    }
    __syncthreads();
    if (tid < SS) {
        float qv[16];
#pragma unroll
        for (int d = 0; d < 16; d++) qv[d] = Qs[tid][d];
        float mx = -1e30f;
        for (int k = 0; k < SS; k++) {
            float sdot = 0.f;
#pragma unroll
            for (int d = 0; d < 16; d++) sdot = fmaf(qv[d], Ks[k][d], sdot);
            mx = fmaxf(mx, sdot * 0.25f);
        }
        float den = 0.f, o[16];
#pragma unroll
        for (int d = 0; d < 16; d++) o[d] = 0.f;
        for (int k = 0; k < SS; k++) {
            float sdot = 0.f;
#pragma unroll
            for (int d = 0; d < 16; d++) sdot = fmaf(qv[d], Ks[k][d], sdot);
            float e = expf(sdot * 0.25f - mx);
            den += e;
#pragma unroll
            for (int d = 0; d < 16; d++) o[d] = fmaf(e, Vs[k][d], o[d]);
        }
        float inv = 1.f / den;
        __half* outp = g_ATTOh + ((size_t)bt * SS + tid) * CC + h * 16;
#pragma unroll
        for (int d = 0; d < 16; d++) outp[d] = __float2half_rn(o[d] * inv);
    }
}

// ---------------- LN3 ------------------------------------------------------
__global__ void k_ln3(const float* __restrict__ g, const float* __restrict__ be)
{
    int row = blockIdx.x;
    int c = threadIdx.x;
    float v = g_XCAT2[(size_t)row * CC + c];
    __shared__ float sh[8];
    float s = v;
    for (int o = 16; o > 0; o >>= 1) s += __shfl_xor_sync(0xffffffffu, s, o);
    if ((c & 31) == 0) sh[c >> 5] = s;
    __syncthreads();
    float mean = (sh[0] + sh[1] + sh[2] + sh[3]) * (1.f / CC);
    float dv = v - mean;
    float q2 = dv * dv;
    for (int o = 16; o > 0; o >>= 1) q2 += __shfl_xor_sync(0xffffffffu, q2, o);
    if ((c & 31) == 0) sh[4 + (c >> 5)] = q2;
    __syncthreads();
    float var = (sh[4] + sh[5] + sh[6] + sh[7]) * (1.f / CC);
    g_XN3h[(size_t)row * CC + c] = __float2half_rn(dv * rsqrtf(var + 1e-5f) * g[c] + be[c]);
}

// ---------------- host launch ----------------------------------------------
#define GEMM_SMEM 65536
static inline void launch_gemm(const __half* A, const __half* W, const float* bias,
                               const float* res, void* out, int M, int N, int K,
                               int epi, int outHalf)
{
    dim3 grid(N / 128, (M + 127) / 128);
    k_gemm_h<<<grid, 256, GEMM_SMEM>>>(A, W, bias, res ? res : (const float*)A,
                                       out, M, N, K, epi, outHalf);
}

extern "C" void kernel_launch(void* const* d_in, const int* in_sizes, int n_in,
                              void* d_out, int out_size)
{
    (void)in_sizes; (void)n_in; (void)out_size;
    const float* x        = (const float*)d_in[0];
    const float* refp     = (const float*)d_in[1];
    const float* pe_buf   = (const float*)d_in[2];
    const float* learn_pos= (const float*)d_in[3];
    const float* w_off    = (const float*)d_in[4];
    const float* b_off    = (const float*)d_in[5];
    const float* w_attn   = (const float*)d_in[6];
    const float* b_attn   = (const float*)d_in[7];
    const float* w_val    = (const float*)d_in[8];
    const float* b_val    = (const float*)d_in[9];
    const float* w_out    = (const float*)d_in[10];
    const float* b_out    = (const float*)d_in[11];
    const float* in_w     = (const float*)d_in[12];
    const float* in_b     = (const float*)d_in[13];
    const float* out_w    = (const float*)d_in[14];
    const float* out_b    = (const float*)d_in[15];
    const float* fc1_w    = (const float*)d_in[16];
    const float* fc1_b    = (const float*)d_in[17];
    const float* fc2_w    = (const float*)d_in[18];
    const float* fc2_b    = (const float*)d_in[19];
    const float* g1       = (const float*)d_in[20];
    const float* be1      = (const float*)d_in[21];
    const float* g2       = (const float*)d_in[22];
    const float* be2      = (const float*)d_in[23];
    const float* g3       = (const float*)d_in[24];
    const float* be3      = (const float*)d_in[25];
    float* out = (float*)d_out;

    cudaFuncSetAttribute(k_gemm_h, cudaFuncAttributeMaxDynamicSharedMemorySize, GEMM_SMEM);

    float *pXS, *pOFF, *pAW, *pVAL, *pXS2, *pXCAT, *pQKV, *pXCAT2;
    __half *pQh, *pXNh, *pOh, *pXN2h, *pATTOh, *pXN3h, *pHIDh, *pWh;
    cudaGetSymbolAddress((void**)&pXS,   g_XS);
    cudaGetSymbolAddress((void**)&pOFF,  g_OFF);
    cudaGetSymbolAddress((void**)&pAW,   g_AW);
    cudaGetSymbolAddress((void**)&pVAL,  g_VAL);
    cudaGetSymbolAddress((void**)&pXS2,  g_XS2);
    cudaGetSymbolAddress((void**)&pXCAT, g_XCAT);
    cudaGetSymbolAddress((void**)&pQKV,  g_QKV);
    cudaGetSymbolAddress((void**)&pXCAT2,g_XCAT2);
    cudaGetSymbolAddress((void**)&pQh,   g_Qh);
    cudaGetSymbolAddress((void**)&pXNh,  g_XNh);
    cudaGetSymbolAddress((void**)&pOh,   g_Oh);
    cudaGetSymbolAddress((void**)&pXN2h, g_XN2h);
    cudaGetSymbolAddress((void**)&pATTOh,g_ATTOh);
    cudaGetSymbolAddress((void**)&pXN3h, g_XN3h);
    cudaGetSymbolAddress((void**)&pHIDh, g_HIDh);
    cudaGetSymbolAddress((void**)&pWh,   g_Wh);

    // 0) weight conversion fp32 -> fp16
    k_cvt_w<<<272, 256>>>(w_off, w_attn, w_val, w_out, in_w, out_w, fc1_w, fc2_w);
    // 1) LN1 + pos-embed (writes XS f32, XNh, Qh)
    k_ln1<<<BLQ, 128>>>(x, pe_buf, learn_pos, g1, be1);
    // 2) offsets GEMM (N=256)
    launch_gemm(pQh,  pWh + WOFF_OFF,  b_off,  nullptr, pOFF, BLQ, 256, CC, 0, 0);
    // 3) attention-weight GEMM (N=128)
    launch_gemm(pQh,  pWh + WOFF_ATTN, b_attn, nullptr, pAW,  BLQ, 128, CC, 0, 0);
    // 4) value GEMM (N=128)
    launch_gemm(pXNh, pWh + WOFF_VAL,  b_val,  nullptr, pVAL, BLQ, 128, CC, 0, 0);
    // 5) deformable sampling (writes Oh)
    k_deform<<<BLQ, 128>>>(refp);
    // 6) output projection + residual
    launch_gemm(pOh,  pWh + WOFF_OUT,  b_out,  pXS,     pXS2, BLQ, 128, CC, 1, 0);
    // 7) concat level-0 + LN2 (writes XCAT f32, XN2h)
    k_xcat_ln2<<<TOK, 128>>>(x, g2, be2);
    // 8) QKV GEMM (N=384)
    launch_gemm(pXN2h, pWh + WOFF_IN,  in_b,   nullptr, pQKV, TOK, 384, CC, 0, 0);
    // 9) self-attention (writes ATTOh)
    k_attn<<<dim3(BB * TT, HH), 128>>>();
    // 10) attention out-proj + residual
    launch_gemm(pATTOh, pWh + WOFF_OUTW, out_b, pXCAT,  pXCAT2, TOK, 128, CC, 1, 0);
    // 11) LN3 (writes XN3h)
    k_ln3<<<TOK, 128>>>(g3, be3);
    // 12) FC1 + GELU (N=512) -> fp16 HID
    launch_gemm(pXN3h, pWh + WOFF_FC1, fc1_b,  nullptr, pHIDh, TOK, 512, CC, 2, 1);
    // 13) FC2 + residual -> final output (K=512)
    launch_gemm(pHIDh, pWh + WOFF_FC2, fc2_b,  pXCAT2, out,   TOK, 128, 512, 1, 0);
}

// round 4
// speedup vs baseline: 2.8523x; 1.1657x over previous
#include <cuda_runtime.h>
#include <cuda_fp16.h>
#include <math.h>
#include <stdint.h>

// Problem constants
#define TT   243
#define PP   17
#define LL   4
#define CC   128
#define HH   8
#define NPT  4
#define DHH  16
#define BB   2
#define LQ   (TT*PP*LL)        // 16524
#define BLQ  (BB*LQ)           // 33048
#define NLVL 5
#define TOK  (BB*TT*PP*NLVL)   // 41310
#define SS   (PP*NLVL)         // 85

// ---------------- scratch (device globals; no allocations) ----------------
__device__ float  g_XS   [(size_t)BLQ*CC];     // residual (fp32)
__device__ float  g_OFFAW[(size_t)BLQ*384];    // fused offsets(256)+attnw(128)
__device__ float  g_XS2  [(size_t)BLQ*CC];
__device__ float  g_XCAT [(size_t)TOK*CC];
__device__ float  g_QKV  [(size_t)TOK*384];
__device__ float  g_XCAT2[(size_t)TOK*CC];
// fp16 activation buffers
__device__ __half g_Qh   [(size_t)BLQ*CC];
__device__ __half g_XNh  [(size_t)BLQ*CC];
__device__ __half g_VALh [(size_t)BLQ*CC];
__device__ __half g_Oh   [(size_t)BLQ*CC];
__device__ __half g_XN2h [(size_t)TOK*CC];
__device__ __half g_ATTOh[(size_t)TOK*CC];
__device__ __half g_XN3h [(size_t)TOK*CC];
__device__ __half g_HIDh [(size_t)TOK*512];
// fp16 weights, packed (off+attn adjacent => fused N=384 GEMM)
#define WOFF_OFF   0
#define WOFF_ATTN  32768
#define WOFF_VAL   49152
#define WOFF_OUT   65536
#define WOFF_IN    81920
#define WOFF_OUTW  131072
#define WOFF_FC1   147456
#define WOFF_FC2   212992
#define WTOTAL     278528
__device__ __half g_Wh[WTOTAL];
__device__ float  g_Bcat[384];                  // packed [b_off; b_attn]

// ---------------- fp16 tensor-core GEMM (BM=64, BN=128, BK=64) -------------
__device__ __forceinline__ void cpa16(uint32_t dst, const void* src, bool valid) {
    int sz = valid ? 16 : 0;
    asm volatile("cp.async.cg.shared.global [%0], [%1], 16, %2;\n"
                 :: "r"(dst), "l"(src), "r"(sz));
}
#define CP_COMMIT() asm volatile("cp.async.commit_group;\n" ::: "memory")
#define CP_WAIT(n)  asm volatile("cp.async.wait_group %0;\n" :: "n"(n) : "memory")

__device__ __forceinline__ void ldm4(uint32_t* r, uint32_t addr) {
    asm volatile("ldmatrix.sync.aligned.m8n8.x4.shared.b16 {%0,%1,%2,%3}, [%4];\n"
                 : "=r"(r[0]), "=r"(r[1]), "=r"(r[2]), "=r"(r[3]) : "r"(addr));
}
__device__ __forceinline__ void mma16(float* c, const uint32_t* a, const uint32_t* b) {
    asm volatile("mma.sync.aligned.m16n8k16.row.col.f32.f16.f16.f32 "
                 "{%0,%1,%2,%3},{%4,%5,%6,%7},{%8,%9},{%0,%1,%2,%3};\n"
                 : "+f"(c[0]), "+f"(c[1]), "+f"(c[2]), "+f"(c[3])
                 : "r"(a[0]), "r"(a[1]), "r"(a[2]), "r"(a[3]), "r"(b[0]), "r"(b[1]));
}

// stage size: A 64x128B = 8KB, B 128x128B = 16KB -> 24KB/stage, 2 stages = 48KB
#define STG 24576

__device__ __forceinline__ void gemm_load_stage(
    const __half* __restrict__ A, const __half* __restrict__ W, uint32_t sb,
    int st, int kt, int row0, int col0, int M, int K, int tid)
{
    const int r0 = tid >> 3, ck = tid & 7;
    const uint32_t base = sb + st * STG;
#pragma unroll
    for (int i = 0; i < 4; i++) {
        int r = r0 + i * 16;
        uint32_t swoff = (uint32_t)(r * 128 + ((ck ^ (r & 7)) * 16));
        int gm = row0 + r;
        cpa16(base + swoff, A + (size_t)gm * K + (size_t)kt * 64 + ck * 8, gm < M);
    }
#pragma unroll
    for (int i = 0; i < 8; i++) {
        int r = r0 + i * 16;
        uint32_t swoff = (uint32_t)(r * 128 + ((ck ^ (r & 7)) * 16));
        cpa16(base + 8192 + swoff,
              W + (size_t)(col0 + r) * K + (size_t)kt * 64 + ck * 8, true);
    }
}

__global__ __launch_bounds__(128, 4) void k_gemm_h(
    const __half* __restrict__ A, const __half* __restrict__ W,
    const float* __restrict__ bias, const float* __restrict__ res,
    void* __restrict__ outp, int M, int N, int K, int epi, int outHalf)
{
    extern __shared__ __align__(1024) char sm[];
    uint32_t sb = (uint32_t)__cvta_generic_to_shared(sm);
    const int tid = threadIdx.x, lane = tid & 31, warp = tid >> 5;
    const int g = lane >> 2, t = lane & 3;
    const int wm = (warp >> 1) * 32, wn = (warp & 1) * 64;
    const int row0 = blockIdx.y * 64, col0 = blockIdx.x * 128;
    const int KT = K >> 6;

    float acc[2][8][4];
#pragma unroll
    for (int mi = 0; mi < 2; mi++)
#pragma unroll
        for (int ni = 0; ni < 8; ni++)
#pragma unroll
            for (int r = 0; r < 4; r++) acc[mi][ni][r] = 0.f;

    gemm_load_stage(A, W, sb, 0, 0, row0, col0, M, K, tid);
    CP_COMMIT();

    for (int kt = 0; kt < KT; kt++) {
        const int s = kt & 1;
        if (kt + 1 < KT) {
            gemm_load_stage(A, W, sb, s ^ 1, kt + 1, row0, col0, M, K, tid);
            CP_COMMIT();
            CP_WAIT(1);
        } else {
            CP_WAIT(0);
        }
        __syncthreads();

        const uint32_t aS = sb + s * STG;
        const uint32_t bS = aS + 8192;
        const int rlow = lane & 15, hi = lane >> 4;
#pragma unroll
        for (int kk = 0; kk < 4; kk++) {
            uint32_t af[2][4];
#pragma unroll
            for (int mi = 0; mi < 2; mi++) {
                int r = wm + mi * 16 + rlow;
                int ck = kk * 2 + hi;
                ldm4(af[mi], aS + (uint32_t)(r * 128 + ((ck ^ (r & 7)) * 16)));
            }
            uint32_t bf[8][2];
#pragma unroll
            for (int nj = 0; nj < 4; nj++) {
                int r = wn + nj * 16 + rlow;
                int ck = kk * 2 + hi;
                uint32_t q[4];
                ldm4(q, bS + (uint32_t)(r * 128 + ((ck ^ (r & 7)) * 16)));
                bf[nj * 2 + 0][0] = q[0]; bf[nj * 2 + 0][1] = q[2];
                bf[nj * 2 + 1][0] = q[1]; bf[nj * 2 + 1][1] = q[3];
            }
#pragma unroll
            for (int mi = 0; mi < 2; mi++)
#pragma unroll
                for (int ni = 0; ni < 8; ni++)
                    mma16(acc[mi][ni], af[mi], bf[ni]);
        }
        __syncthreads();
    }

#pragma unroll
    for (int mi = 0; mi < 2; mi++) {
#pragma unroll
        for (int r = 0; r < 2; r++) {
            const int gm = row0 + wm + mi * 16 + g + r * 8;
            if (gm >= M) continue;
            const float* rp = res + (size_t)gm * N;
#pragma unroll
            for (int ni = 0; ni < 8; ni++) {
                const int gn = col0 + wn + ni * 8 + 2 * t;
                float v0 = acc[mi][ni][r * 2 + 0] + bias[gn];
                float v1 = acc[mi][ni][r * 2 + 1] + bias[gn + 1];
                if (epi == 1) {
                    v0 += rp[gn];
                    v1 += rp[gn + 1];
                } else if (epi == 2) {
                    v0 = 0.5f * v0 * (1.0f + erff(v0 * 0.7071067811865475f));
                    v1 = 0.5f * v1 * (1.0f + erff(v1 * 0.7071067811865475f));
                }
                if (outHalf) {
                    *(__half2*)((__half*)outp + (size_t)gm * N + gn) = __floats2half2_rn(v0, v1);
                } else {
                    *(float2*)((float*)outp + (size_t)gm * N + gn) = make_float2(v0, v1);
                }
            }
        }
    }
}

// ---------------- weight conversion + bias pack ----------------------------
__global__ void k_cvt_w(const float* __restrict__ w0, const float* __restrict__ w1,
                        const float* __restrict__ w2, const float* __restrict__ w3,
                        const float* __restrict__ w4, const float* __restrict__ w5,
                        const float* __restrict__ w6, const float* __restrict__ w7,
                        const float* __restrict__ b_off, const float* __restrict__ b_attn)
{
    if (blockIdx.x == 0 && threadIdx.x < 384)
        g_Bcat[threadIdx.x] = threadIdx.x < 256 ? b_off[threadIdx.x] : b_attn[threadIdx.x - 256];
    for (int idx = blockIdx.x * blockDim.x + threadIdx.x; idx < WTOTAL;
         idx += gridDim.x * blockDim.x) {
        const float* src; int off;
        if      (idx < WOFF_ATTN) { src = w0; off = idx; }
        else if (idx < WOFF_VAL ) { src = w1; off = idx - WOFF_ATTN; }
        else if (idx < WOFF_OUT ) { src = w2; off = idx - WOFF_VAL; }
        else if (idx < WOFF_IN  ) { src = w3; off = idx - WOFF_OUT; }
        else if (idx < WOFF_OUTW) { src = w4; off = idx - WOFF_IN; }
        else if (idx < WOFF_FC1 ) { src = w5; off = idx - WOFF_OUTW; }
        else if (idx < WOFF_FC2 ) { src = w6; off = idx - WOFF_FC1; }
        else                      { src = w7; off = idx - WOFF_FC2; }
        g_Wh[idx] = __float2half_rn(src[off]);
    }
}

// ---------------- LN1 + positional embedding -------------------------------
__global__ void k_ln1(const float* __restrict__ x, const float* __restrict__ pe,
                      const float* __restrict__ lp, const float* __restrict__ g,
                      const float* __restrict__ be)
{
    int row = blockIdx.x;
    int b = row / LQ; int lq = row - b * LQ;
    int l = lq & 3; int tp = lq >> 2; int p = tp % PP; int t = tp / PP;
    int c = threadIdx.x;
    size_t xi = ((((size_t)((b * TT + t) * PP + p)) * (LL + 1)) + (l + 1)) * CC + c;
    float v = x[xi];
    g_XS[(size_t)row * CC + c] = v;

    __shared__ float sh[8];
    float s = v;
    for (int o = 16; o > 0; o >>= 1) s += __shfl_xor_sync(0xffffffffu, s, o);
    if ((c & 31) == 0) sh[c >> 5] = s;
    __syncthreads();
    float mean = (sh[0] + sh[1] + sh[2] + sh[3]) * (1.f / CC);
    float dv = v - mean;
    float q2 = dv * dv;
    for (int o = 16; o > 0; o >>= 1) q2 += __shfl_xor_sync(0xffffffffu, q2, o);
    if ((c & 31) == 0) sh[4 + (c >> 5)] = q2;
    __syncthreads();
    float var = (sh[4] + sh[5] + sh[6] + sh[7]) * (1.f / CC);
    float xn = dv * rsqrtf(var + 1e-5f) * g[c] + be[c];
    g_XNh[(size_t)row * CC + c] = __float2half_rn(xn);
    g_Qh [(size_t)row * CC + c] = __float2half_rn(xn + pe[(size_t)lq * CC + c] + lp[(size_t)lq * CC + c]);
}

// ---------------- deformable sampling (half2, 2 rows/block) ----------------
__global__ void k_deform(const float* __restrict__ refp)
{
    int row = blockIdx.x * 2 + (threadIdx.x >> 6);
    int s = threadIdx.x & 63;
    int b = row / LQ; int lq = row - b * LQ;
    int tp = lq >> 2; int p = tp % PP; int t = tp / PP;
    int h = s >> 3, d2 = (s & 7) * 2;
    float refx = refp[(((size_t)b * TT + t) * PP + p) * 2 + 0];
    float refy = refp[(((size_t)b * TT + t) * PP + p) * 2 + 1];

    const float* awp = g_OFFAW + (size_t)row * 384 + 256 + h * 16;
    float w[16], mx = -1e30f;
#pragma unroll
    for (int i = 0; i < 16; i++) { w[i] = awp[i]; mx = fmaxf(mx, w[i]); }
    float den = 0.f;
#pragma unroll
    for (int i = 0; i < 16; i++) { w[i] = expf(w[i] - mx); den += w[i]; }
    float inv = 1.f / den;

    const float*  offp  = g_OFFAW + (size_t)row * 384 + h * 32;
    const __half* vbase = g_VALh + (size_t)b * LQ * CC + h * 16 + d2;
    float a0 = 0.f, a1 = 0.f;
#pragma unroll
    for (int l = 0; l < LL; l++) {
#pragma unroll
        for (int pt = 0; pt < NPT; pt++) {
            float ox = offp[(l * 4 + pt) * 2 + 0];
            float oy = offp[(l * 4 + pt) * 2 + 1];
            float fx = refx * PP + ox - 0.5f;
            float fy = refy * TT + oy - 0.5f;
            float x0f = floorf(fx), y0f = floorf(fy);
            int x0 = (int)x0f, y0 = (int)y0f;
            float wx1 = fx - x0f, wy1 = fy - y0f;
            float wx0 = 1.f - wx1, wy0 = 1.f - wy1;
            bool xi0 = (x0 >= 0) && (x0 < PP);
            bool xi1 = (x0 + 1 >= 0) && (x0 + 1 < PP);
            bool yi0 = (y0 >= 0) && (y0 < TT);
            bool yi1 = (y0 + 1 >= 0) && (y0 + 1 < TT);
            float2 v00 = make_float2(0.f, 0.f), v01 = v00, v10 = v00, v11 = v00;
            if (yi0 && xi0) v00 = __half22float2(*(const __half2*)(vbase + ((size_t)(y0 * PP + x0) * LL + l) * CC));
            if (yi0 && xi1) v01 = __half22float2(*(const __half2*)(vbase + ((size_t)(y0 * PP + x0 + 1) * LL + l) * CC));
            if (yi1 && xi0) v10 = __half22float2(*(const __half2*)(vbase + ((size_t)((y0 + 1) * PP + x0) * LL + l) * CC));
            if (yi1 && xi1) v11 = __half22float2(*(const __half2*)(vbase + ((size_t)((y0 + 1) * PP + x0 + 1) * LL + l) * CC));
            float ww = w[l * 4 + pt];
            float s0 = v00.x * wy0 * wx0 + v01.x * wy0 * wx1 + v10.x * wy1 * wx0 + v11.x * wy1 * wx1;
            float s1 = v00.y * wy0 * wx0 + v01.y * wy0 * wx1 + v10.y * wy1 * wx0 + v11.y * wy1 * wx1;
            a0 = fmaf(s0, ww, a0);
            a1 = fmaf(s1, ww, a1);
        }
    }
    *(__half2*)(g_Oh + (size_t)row * CC + h * 16 + d2) = __floats2half2_rn(a0 * inv, a1 * inv);
}

// ---------------- build xcat + LN2 -----------------------------------------
__global__ void k_xcat_ln2(const float* __restrict__ x, const float* __restrict__ g,
                           const float* __restrict__ be)
{
    int row = blockIdx.x;
    int lvl = row % 5; int btp = row / 5;
    int c = threadIdx.x;
    float v;
    if (lvl == 0) {
        v = x[((size_t)btp * NLVL) * CC + c];
    } else {
        int p = btp % PP; int bt = btp / PP; int b = bt / TT; int t = bt % TT;
        size_t rxs = (size_t)b * LQ + ((size_t)t * PP + p) * LL + (lvl - 1);
        v = g_XS2[rxs * CC + c];
    }
    g_XCAT[(size_t)row * CC + c] = v;

    __shared__ float sh[8];
    float s = v;
    for (int o = 16; o > 0; o >>= 1) s += __shfl_xor_sync(0xffffffffu, s, o);
    if ((c & 31) == 0) sh[c >> 5] = s;
    __syncthreads();
    float mean = (sh[0] + sh[1] + sh[2] + sh[3]) * (1.f / CC);
    float dv = v - mean;
    float q2 = dv * dv;
    for (int o = 16; o > 0; o >>= 1) q2 += __shfl_xor_sync(0xffffffffu, q2, o);
    if ((c & 31) == 0) sh[4 + (c >> 5)] = q2;
    __syncthreads();
    float var = (sh[4] + sh[5] + sh[6] + sh[7]) * (1.f / CC);
    g_XN2h[(size_t)row * CC + c] = __float2half_rn(dv * rsqrtf(var + 1e-5f) * g[c] + be[c]);
}

// ---------------- per-(bt,head) self-attention -----------------------------
__global__ void k_attn()
{
    int bt = blockIdx.x, h = blockIdx.y;
    __shared__ float Qs[SS][DHH], Ks[SS][DHH], Vs[SS][DHH];
    int tid = threadIdx.x;
    for (int i = tid; i < SS * DHH; i += 128) {
        int s = i >> 4, d = i & 15;
        const float* base = g_QKV + ((size_t)bt * SS + s) * 384 + h * 16 + d;
        Qs[s][d] = base[0];
        Ks[s][d] = base[128];
        Vs[s][d] = base[256];
    }
    __syncthreads();
    if (tid < SS) {
        float qv[16];
#pragma unroll
        for (int d = 0; d < 16; d++) qv[d] = Qs[tid][d];
        float mx = -1e30f;
        for (int k = 0; k < SS; k++) {
            float sdot = 0.f;
#pragma unroll
            for (int d = 0; d < 16; d++) sdot = fmaf(qv[d], Ks[k][d], sdot);
            mx = fmaxf(mx, sdot * 0.25f);
        }
        float den = 0.f, o[16];
#pragma unroll
        for (int d = 0; d < 16; d++) o[d] = 0.f;
        for (int k = 0; k < SS; k++) {
            float sdot = 0.f;
#pragma unroll
            for (int d = 0; d < 16; d++) sdot = fmaf(qv[d], Ks[k][d], sdot);
            float e = expf(sdot * 0.25f - mx);
            den += e;
#pragma unroll
            for (int d = 0; d < 16; d++) o[d] = fmaf(e, Vs[k][d], o[d]);
        }
        float inv = 1.f / den;
        __half* outp = g_ATTOh + ((size_t)bt * SS + tid) * CC + h * 16;
#pragma unroll
        for (int d = 0; d < 16; d++) outp[d] = __float2half_rn(o[d] * inv);
    }
}

// ---------------- LN3 ------------------------------------------------------
__global__ void k_ln3(const float* __restrict__ g, const float* __restrict__ be)
{
    int row = blockIdx.x;
    int c = threadIdx.x;
    float v = g_XCAT2[(size_t)row * CC + c];
    __shared__ float sh[8];
    float s = v;
    for (int o = 16; o > 0; o >>= 1) s += __shfl_xor_sync(0xffffffffu, s, o);
    if ((c & 31) == 0) sh[c >> 5] = s;
    __syncthreads();
    float mean = (sh[0] + sh[1] + sh[2] + sh[3]) * (1.f / CC);
    float dv = v - mean;
    float q2 = dv * dv;
    for (int o = 16; o > 0; o >>= 1) q2 += __shfl_xor_sync(0xffffffffu, q2, o);
    if ((c & 31) == 0) sh[4 + (c >> 5)] = q2;
    __syncthreads();
    float var = (sh[4] + sh[5] + sh[6] + sh[7]) * (1.f / CC);
    g_XN3h[(size_t)row * CC + c] = __float2half_rn(dv * rsqrtf(var + 1e-5f) * g[c] + be[c]);
}

// ---------------- host launch ----------------------------------------------
#define GEMM_SMEM 49152
static inline void launch_gemm(const __half* A, const __half* W, const float* bias,
                               const float* res, void* out, int M, int N, int K,
                               int epi, int outHalf)
{
    dim3 grid(N / 128, (M + 63) / 64);
    k_gemm_h<<<grid, 128, GEMM_SMEM>>>(A, W, bias, res ? res : (const float*)A,
                                       out, M, N, K, epi, outHalf);
}

extern "C" void kernel_launch(void* const* d_in, const int* in_sizes, int n_in,
                              void* d_out, int out_size)
{
    (void)in_sizes; (void)n_in; (void)out_size;
    const float* x        = (const float*)d_in[0];
    const float* refp     = (const float*)d_in[1];
    const float* pe_buf   = (const float*)d_in[2];
    const float* learn_pos= (const float*)d_in[3];
    const float* w_off    = (const float*)d_in[4];
    const float* b_off    = (const float*)d_in[5];
    const float* w_attn   = (const float*)d_in[6];
    const float* b_attn   = (const float*)d_in[7];
    const float* w_val    = (const float*)d_in[8];
    const float* b_val    = (const float*)d_in[9];
    const float* w_out    = (const float*)d_in[10];
    const float* b_out    = (const float*)d_in[11];
    const float* in_w     = (const float*)d_in[12];
    const float* in_b     = (const float*)d_in[13];
    const float* out_w    = (const float*)d_in[14];
    const float* out_b    = (const float*)d_in[15];
    const float* fc1_w    = (const float*)d_in[16];
    const float* fc1_b    = (const float*)d_in[17];
    const float* fc2_w    = (const float*)d_in[18];
    const float* fc2_b    = (const float*)d_in[19];
    const float* g1       = (const float*)d_in[20];
    const float* be1      = (const float*)d_in[21];
    const float* g2       = (const float*)d_in[22];
    const float* be2      = (const float*)d_in[23];
    const float* g3       = (const float*)d_in[24];
    const float* be3      = (const float*)d_in[25];
    float* out = (float*)d_out;

    cudaFuncSetAttribute(k_gemm_h, cudaFuncAttributeMaxDynamicSharedMemorySize, GEMM_SMEM);

    float *pXS, *pOFFAW, *pXS2, *pXCAT, *pQKV, *pXCAT2, *pBcat;
    __half *pQh, *pXNh, *pVALh, *pOh, *pXN2h, *pATTOh, *pXN3h, *pHIDh, *pWh;
    cudaGetSymbolAddress((void**)&pXS,    g_XS);
    cudaGetSymbolAddress((void**)&pOFFAW, g_OFFAW);
    cudaGetSymbolAddress((void**)&pXS2,   g_XS2);
    cudaGetSymbolAddress((void**)&pXCAT,  g_XCAT);
    cudaGetSymbolAddress((void**)&pQKV,   g_QKV);
    cudaGetSymbolAddress((void**)&pXCAT2, g_XCAT2);
    cudaGetSymbolAddress((void**)&pBcat,  g_Bcat);
    cudaGetSymbolAddress((void**)&pQh,    g_Qh);
    cudaGetSymbolAddress((void**)&pXNh,   g_XNh);
    cudaGetSymbolAddress((void**)&pVALh,  g_VALh);
    cudaGetSymbolAddress((void**)&pOh,    g_Oh);
    cudaGetSymbolAddress((void**)&pXN2h,  g_XN2h);
    cudaGetSymbolAddress((void**)&pATTOh, g_ATTOh);
    cudaGetSymbolAddress((void**)&pXN3h,  g_XN3h);
    cudaGetSymbolAddress((void**)&pHIDh,  g_HIDh);
    cudaGetSymbolAddress((void**)&pWh,    g_Wh);

    // 0) weight conversion + bias pack
    k_cvt_w<<<272, 256>>>(w_off, w_attn, w_val, w_out, in_w, out_w, fc1_w, fc2_w,
                          b_off, b_attn);
    // 1) LN1 + pos-embed
    k_ln1<<<BLQ, 128>>>(x, pe_buf, learn_pos, g1, be1);
    // 2) fused offsets+attnw GEMM (N=384)
    launch_gemm(pQh,  pWh + WOFF_OFF,  pBcat,  nullptr, pOFFAW, BLQ, 384, CC, 0, 0);
    // 3) value GEMM (N=128) -> fp16
    launch_gemm(pXNh, pWh + WOFF_VAL,  b_val,  nullptr, pVALh,  BLQ, 128, CC, 0, 1);
    // 4) deformable sampling (half2, 2 rows/block)
    k_deform<<<BLQ / 2, 128>>>(refp);
    // 5) output projection + residual
    launch_gemm(pOh,  pWh + WOFF_OUT,  b_out,  pXS,     pXS2,   BLQ, 128, CC, 1, 0);
    // 6) concat level-0 + LN2
    k_xcat_ln2<<<TOK, 128>>>(x, g2, be2);
    // 7) QKV GEMM (N=384)
    launch_gemm(pXN2h, pWh + WOFF_IN,  in_b,   nullptr, pQKV,   TOK, 384, CC, 0, 0);
    // 8) self-attention
    k_attn<<<dim3(BB * TT, HH), 128>>>();
    // 9) attention out-proj + residual
    launch_gemm(pATTOh, pWh + WOFF_OUTW, out_b, pXCAT,  pXCAT2, TOK, 128, CC, 1, 0);
    // 10) LN3
    k_ln3<<<TOK, 128>>>(g3, be3);
    // 11) FC1 + GELU (N=512) -> fp16
    launch_gemm(pXN3h, pWh + WOFF_FC1, fc1_b,  nullptr, pHIDh,  TOK, 512, CC, 2, 1);
    // 12) FC2 + residual -> final output (K=512)
    launch_gemm(pHIDh, pWh + WOFF_FC2, fc2_b,  pXCAT2, out,    TOK, 128, 512, 1, 0);
}